// round 12
// baseline (speedup 1.0000x reference)
#include <cuda_runtime.h>
#include <cstdint>

// Problem constants
#define BB 8
#define TT 1024
#define CC 768
#define HH 12
#define DD 64
#define NTOK (BB * TT)      // 8192
#define NQKV (3 * CC)       // 2304

// Scratch (device globals; no runtime allocation allowed)
__device__ float g_q[BB * HH * TT * DD];   // [B,H,T,D], q pre-scaled by log2e/8
__device__ float g_k[BB * HH * TT * DD];
__device__ float g_v[BB * HH * TT * DD];
__device__ float g_y[BB * TT * CC];        // attention output (tf32-rounded)
__device__ float g_xc[NTOK * CC];          // x, tf32-rounded
__device__ float g_wqc[CC * NQKV];         // w_qkv, tf32-rounded
__device__ float g_wpc[CC * CC];           // w_proj, tf32-rounded

// ---------------------------------------------------------------------------
// Helpers (compute_80-level PTX only; no sm_103a-only features)
// ---------------------------------------------------------------------------
__device__ __forceinline__ uint32_t smem_u32(const void* p) {
    uint32_t a;
    asm("{ .reg .u64 t; cvta.to.shared.u64 t, %1; cvt.u32.u64 %0, t; }"
        : "=r"(a) : "l"(p));
    return a;
}
__device__ __forceinline__ uint32_t tf32_bits(float x) {
    uint32_t r;
    asm("cvt.rna.tf32.f32 %0, %1;" : "=r"(r) : "f"(x));
    return r;
}
__device__ __forceinline__ float tf32_round(float x) {
    return __uint_as_float(tf32_bits(x));
}
__device__ __forceinline__ float ex2(float x) {
    float y;
    asm("ex2.approx.ftz.f32 %0, %1;" : "=f"(y) : "f"(x));
    return y;
}
__device__ __forceinline__ void cp_async16(uint32_t dst, const void* src) {
    asm volatile("cp.async.ca.shared.global [%0], [%1], 16;"
                 :: "r"(dst), "l"(src));
}
#define CP_COMMIT() asm volatile("cp.async.commit_group;" ::: "memory")
#define CP_WAIT(n)  asm volatile("cp.async.wait_group %0;" :: "n"(n) : "memory")

// m16n8k8 tf32 mma: D += A*B, fp32 accumulate.
__device__ __forceinline__ void mma_tf32(float* d, const uint32_t* a,
                                         const uint32_t* b) {
    asm volatile(
        "mma.sync.aligned.m16n8k8.row.col.f32.tf32.tf32.f32 "
        "{%0,%1,%2,%3}, {%4,%5,%6,%7}, {%8,%9}, {%0,%1,%2,%3};"
        : "+f"(d[0]), "+f"(d[1]), "+f"(d[2]), "+f"(d[3])
        : "r"(a[0]), "r"(a[1]), "r"(a[2]), "r"(a[3]),
          "r"(b[0]), "r"(b[1]));
}

// ---------------------------------------------------------------------------
// Single fused tf32 rounding pass over x, w_qkv, w_proj.
// ---------------------------------------------------------------------------
#define N4_X  (NTOK * CC / 4)     // 1572864
#define N4_WQ (CC * NQKV / 4)     // 442368
#define N4_WP (CC * CC / 4)       // 147456
#define CVT_BLOCKS ((N4_X + N4_WQ + N4_WP) / 256)   // 8448

__global__ __launch_bounds__(256) void cvt_all_kernel(
    const float* __restrict__ x, const float* __restrict__ wq,
    const float* __restrict__ wp)
{
    int i = blockIdx.x * 256 + threadIdx.x;
    const float* src;
    float* dst;
    if (i < N4_X) {
        src = x; dst = g_xc;
    } else if (i < N4_X + N4_WQ) {
        i -= N4_X; src = wq; dst = g_wqc;
    } else {
        i -= N4_X + N4_WQ; src = wp; dst = g_wpc;
    }
    float4 v = ((const float4*)src)[i];
    uint4 r;
    r.x = tf32_bits(v.x);
    r.y = tf32_bits(v.y);
    r.z = tf32_bits(v.z);
    r.w = tf32_bits(v.w);
    ((uint4*)dst)[i] = r;
}

// ---------------------------------------------------------------------------
// tf32 mma.sync GEMM: out[M,Ntot] = A[M,768] @ W[768,Ntot] + bias
// CTA tile 128x128 with 128 THREADS (4 warps as 2m x 2n), warp tile 64x64:
//   smem traffic = 128 B per MMA = 1 smem-cyc : 1 tensor-cyc (balanced),
//   ~190 regs/thread -> 2 CTAs/SM retained (128-thr blocks: 256-reg budget).
// 3-stage cp.async pipeline (105 KB smem/CTA; 2 CTAs = 210 KB <= 228 KB).
// As: m-major [128][36]  (frag bank = 4g+c4, perfect permutation)
// Bs: k-major [32][136]  (136 = 8 mod 32 -> frag bank = 8c4+g, perfect)
// mode 0: QKV epilogue (scatter to g_q/g_k/g_v; q * log2e/8, tf32-rounded)
// mode 1: row-major store to out
// ---------------------------------------------------------------------------
#define KTILE 32
#define NIT (CC / KTILE)        // 24
#define ASTRIDE 36
#define BSTRIDE 136
#define ABYTES (128 * ASTRIDE * 4)   // 18432
#define BBYTES (KTILE * BSTRIDE * 4) // 17408
#define BUFBYTES (ABYTES + BBYTES)   // 35840
#define NSTAGE 3
#define SMEMB (NSTAGE * BUFBYTES)    // 107520

__device__ __forceinline__ void mm_issue_tile(
    const float* __restrict__ A, const float* __restrict__ W,
    uint32_t sbuf, int m0, int n0, int k0, int Ntot, int tid)
{
    const uint32_t sA = sbuf;
    const uint32_t sB = sbuf + ABYTES;
#pragma unroll
    for (int i = 0; i < 8; i++) {
        int idx = tid + 128 * i;
        int m = idx >> 3, kq = idx & 7;
        cp_async16(sA + (m * ASTRIDE + kq * 4) * 4,
                   A + (size_t)(m0 + m) * CC + k0 + kq * 4);
    }
#pragma unroll
    for (int i = 0; i < 8; i++) {
        int idx = tid + 128 * i;
        int n4 = idx & 31, k = idx >> 5;
        cp_async16(sB + (k * BSTRIDE + n4 * 4) * 4,
                   W + (size_t)(k0 + k) * Ntot + n0 + n4 * 4);
    }
    CP_COMMIT();
}

__global__ void __launch_bounds__(128, 2) mm_mma_kernel(
    const float* __restrict__ bias, float* __restrict__ out,
    int Ntot, int mode)
{
    extern __shared__ __align__(16) char smem[];
    const float* A = (mode == 0) ? g_xc : g_y;
    const float* W = (mode == 0) ? g_wqc : g_wpc;

    const int tid = threadIdx.x;
    const int wid = tid >> 5;      // 0..3
    const int lane = tid & 31;
    const int g = lane >> 2;       // 0..7
    const int c4 = lane & 3;       // 0..3
    const int m0 = blockIdx.y * 128;
    const int n0 = blockIdx.x * 128;
    const int wm = (wid >> 1) * 64;       // 0 or 64
    const int wn = (wid & 1) * 64;        // 0 or 64
    const uint32_t sbase = smem_u32(smem);

    float acc[4][8][4];
#pragma unroll
    for (int mt = 0; mt < 4; mt++)
#pragma unroll
        for (int nt = 0; nt < 8; nt++)
#pragma unroll
            for (int i = 0; i < 4; i++) acc[mt][nt][i] = 0.0f;

    // Prologue: stages 0 and 1 in flight.
    mm_issue_tile(A, W, sbase, m0, n0, 0, Ntot, tid);
    mm_issue_tile(A, W, sbase + BUFBYTES, m0, n0, KTILE, Ntot, tid);

    int buf = 0;      // stage holding tile t
    int fill = 2;     // stage to fill with tile t+2

    for (int t = 0; t < NIT; t++) {
        if (t + 2 < NIT) {
            mm_issue_tile(A, W, sbase + fill * BUFBYTES,
                          m0, n0, (t + 2) * KTILE, Ntot, tid);
            fill = (fill == 2) ? 0 : fill + 1;
            CP_WAIT(2);
        } else if (t + 1 < NIT) {
            CP_WAIT(1);
        } else {
            CP_WAIT(0);
        }
        __syncthreads();

        const float* Asp = (const float*)(smem + buf * BUFBYTES);
        const float* Bsp = (const float*)(smem + buf * BUFBYTES + ABYTES);

#pragma unroll
        for (int kk8 = 0; kk8 < 4; kk8++) {
            const int kk = kk8 * 8;
            uint32_t fa[4][4], fb[8][2];
#pragma unroll
            for (int mt = 0; mt < 4; mt++) {
                const float* p = Asp + (wm + mt * 16 + g) * ASTRIDE + kk + c4;
                fa[mt][0] = __float_as_uint(p[0]);
                fa[mt][1] = __float_as_uint(p[8 * ASTRIDE]);
                fa[mt][2] = __float_as_uint(p[4]);
                fa[mt][3] = __float_as_uint(p[8 * ASTRIDE + 4]);
            }
#pragma unroll
            for (int nt = 0; nt < 8; nt++) {
                const float* q = Bsp + (kk + c4) * BSTRIDE + wn + nt * 8 + g;
                fb[nt][0] = __float_as_uint(q[0]);
                fb[nt][1] = __float_as_uint(q[4 * BSTRIDE]);
            }
#pragma unroll
            for (int mt = 0; mt < 4; mt++)
#pragma unroll
                for (int nt = 0; nt < 8; nt++)
                    mma_tf32(acc[mt][nt], fa[mt], fb[nt]);
        }
        __syncthreads();
        buf = (buf == 2) ? 0 : buf + 1;
    }

    // Epilogue.  Fragment (mt,nt): rows g,g+8; cols 2c4,2c4+1.
    if (mode == 1) {
#pragma unroll
        for (int mt = 0; mt < 4; mt++) {
#pragma unroll
            for (int nt = 0; nt < 8; nt++) {
                int mg = m0 + wm + mt * 16 + g;
                int ng = n0 + wn + nt * 8 + 2 * c4;
                float b0 = bias[ng], b1 = bias[ng + 1];
                float2 v0 = make_float2(acc[mt][nt][0] + b0, acc[mt][nt][1] + b1);
                float2 v1 = make_float2(acc[mt][nt][2] + b0, acc[mt][nt][3] + b1);
                *(float2*)(out + (size_t)mg * CC + ng) = v0;
                *(float2*)(out + (size_t)(mg + 8) * CC + ng) = v1;
            }
        }
    } else {
        // q scale folds 1/sqrt(64) AND log2(e): attention softmax uses ex2.
#pragma unroll
        for (int mt = 0; mt < 4; mt++) {
#pragma unroll
            for (int nt = 0; nt < 8; nt++) {
                int mg = m0 + wm + mt * 16 + g;
                int ng = n0 + wn + nt * 8 + 2 * c4;
                int region = ng / CC;             // 0=q 1=k 2=v
                int cp = ng - region * CC;
                int h = cp >> 6, d = cp & 63;
                float sc = (region == 0) ? 0.18033688011112042f : 1.0f;
                float* base = (region == 0) ? g_q : (region == 1) ? g_k : g_v;
                int bi = mg >> 10, t = mg & 1023;
                float* dst = base + ((size_t)(bi * HH + h) * TT + t) * DD + d;
                float b0 = bias[ng], b1 = bias[ng + 1];
                float2 v0 = make_float2(tf32_round((acc[mt][nt][0] + b0) * sc),
                                        tf32_round((acc[mt][nt][1] + b1) * sc));
                float2 v1 = make_float2(tf32_round((acc[mt][nt][2] + b0) * sc),
                                        tf32_round((acc[mt][nt][3] + b1) * sc));
                *(float2*)dst = v0;
                *(float2*)(dst + 8 * DD) = v1;
            }
        }
    }
}

// ---------------------------------------------------------------------------
// Causal flash attention on tf32 mma.sync (proven R9 kernel, unchanged).
// ---------------------------------------------------------------------------
#define AKV 64
#define QSTR 68
#define KSTR 68
#define VSTR 72
#define PSTR 68
#define PS_OFF (128 * QSTR)                 // 8704
#define KV_OFF (PS_OFF + 128 * PSTR)        // 17408
#define KBUF_F (AKV * KSTR)                 // 4352
#define KVBUF_F (KBUF_F + AKV * VSTR)       // 8960
#define ATT_SMEMF (KV_OFF + 2 * KVBUF_F)    // 35328
#define ATT_SMEMB (ATT_SMEMF * 4)           // 141312

__global__ __launch_bounds__(256, 1) void attn_mma_kernel()
{
    extern __shared__ __align__(16) float sm[];
    const int tid = threadIdx.x;
    const int wid = tid >> 5;
    const int lane = tid & 31;
    const int g = lane >> 2;      // 0..7
    const int c4 = lane & 3;      // 0..3
    const int qt = 7 - (int)blockIdx.x;   // heavy tiles launch first
    const int bh = blockIdx.y;
    const int q0 = qt * 128;

    const float* Qg = g_q + (size_t)bh * (TT * DD) + (size_t)q0 * DD;
    const float* Kg = g_k + (size_t)bh * (TT * DD);
    const float* Vg = g_v + (size_t)bh * (TT * DD);
    const uint32_t sb = smem_u32(sm);

    // Prologue: Q tile (128x64) + KV tile 0, one cp.async group.
#pragma unroll
    for (int i = 0; i < 8; i++) {
        int idx = tid + 256 * i;
        int r = idx >> 4, c = (idx & 15) * 4;
        cp_async16(sb + (r * QSTR + c) * 4, Qg + r * DD + c);
    }
#pragma unroll
    for (int i = 0; i < 4; i++) {
        int idx = tid + 256 * i;
        int r = idx >> 4, c = (idx & 15) * 4;
        cp_async16(sb + (KV_OFF + r * KSTR + c) * 4, Kg + r * DD + c);
        cp_async16(sb + (KV_OFF + KBUF_F + r * VSTR + c) * 4, Vg + r * DD + c);
    }
    CP_COMMIT();

    float o[8][4];
#pragma unroll
    for (int nt = 0; nt < 8; nt++)
#pragma unroll
        for (int i = 0; i < 4; i++) o[nt][i] = 0.0f;
    float m0 = -1e30f, m1 = -1e30f, l0 = 0.0f, l1 = 0.0f;

    const int ntiles = 2 * qt + 2;

    for (int j = 0; j < ntiles; j++) {
        const int buf = j & 1;
        if (j + 1 < ntiles) {
            const float* Kg2 = Kg + (size_t)(j + 1) * AKV * DD;
            const float* Vg2 = Vg + (size_t)(j + 1) * AKV * DD;
            const uint32_t kvb = sb + (KV_OFF + (buf ^ 1) * KVBUF_F) * 4;
#pragma unroll
            for (int i = 0; i < 4; i++) {
                int idx = tid + 256 * i;
                int r = idx >> 4, c = (idx & 15) * 4;
                cp_async16(kvb + (r * KSTR + c) * 4, Kg2 + r * DD + c);
                cp_async16(kvb + (KBUF_F + r * VSTR + c) * 4, Vg2 + r * DD + c);
            }
            CP_COMMIT();
            CP_WAIT(1);
        } else {
            CP_WAIT(0);
        }
        __syncthreads();

        const float* Ksp = sm + KV_OFF + buf * KVBUF_F;
        const float* Vsp = Ksp + KBUF_F;
        const float* Qsp = sm + (wid * 16 + g) * QSTR;

        // S = Q @ K^T  (log2 domain; Q pre-scaled)
        float s[8][4];
#pragma unroll
        for (int nt = 0; nt < 8; nt++)
#pragma unroll
            for (int i = 0; i < 4; i++) s[nt][i] = 0.0f;

#pragma unroll
        for (int kk = 0; kk < 64; kk += 8) {
            uint32_t a[4];
            const float* qp = Qsp + kk + c4;
            a[0] = __float_as_uint(qp[0]);
            a[1] = __float_as_uint(qp[8 * QSTR]);
            a[2] = __float_as_uint(qp[4]);
            a[3] = __float_as_uint(qp[8 * QSTR + 4]);
#pragma unroll
            for (int nt = 0; nt < 8; nt++) {
                uint32_t b[2];
                const float* kp = Ksp + (nt * 8 + g) * KSTR + kk + c4;
                b[0] = __float_as_uint(kp[0]);
                b[1] = __float_as_uint(kp[4]);
                mma_tf32(s[nt], a, b);
            }
        }

        // Causal mask (only the two diagonal-straddling tiles need it)
        if (j >= 2 * qt) {
            const int off = q0 - j * AKV;   // 0 or -64
            const int r0 = wid * 16 + g, r1 = r0 + 8;
#pragma unroll
            for (int nt = 0; nt < 8; nt++) {
                int col = nt * 8 + 2 * c4;
                if (col     > r0 + off) s[nt][0] = -1e30f;
                if (col + 1 > r0 + off) s[nt][1] = -1e30f;
                if (col     > r1 + off) s[nt][2] = -1e30f;
                if (col + 1 > r1 + off) s[nt][3] = -1e30f;
            }
        }

        // Online softmax (rows g and g+8; quad-wide reduction)
        float mx0 = -1e30f, mx1 = -1e30f;
#pragma unroll
        for (int nt = 0; nt < 8; nt++) {
            mx0 = fmaxf(mx0, fmaxf(s[nt][0], s[nt][1]));
            mx1 = fmaxf(mx1, fmaxf(s[nt][2], s[nt][3]));
        }
        mx0 = fmaxf(mx0, __shfl_xor_sync(0xffffffffu, mx0, 1));
        mx0 = fmaxf(mx0, __shfl_xor_sync(0xffffffffu, mx0, 2));
        mx1 = fmaxf(mx1, __shfl_xor_sync(0xffffffffu, mx1, 1));
        mx1 = fmaxf(mx1, __shfl_xor_sync(0xffffffffu, mx1, 2));

        float mn0 = fmaxf(m0, mx0), mn1 = fmaxf(m1, mx1);
        float corr0 = ex2(m0 - mn0), corr1 = ex2(m1 - mn1);
        m0 = mn0; m1 = mn1;

        float sum0 = 0.0f, sum1 = 0.0f;
#pragma unroll
        for (int nt = 0; nt < 8; nt++) {
            s[nt][0] = ex2(s[nt][0] - m0);
            s[nt][1] = ex2(s[nt][1] - m0);
            s[nt][2] = ex2(s[nt][2] - m1);
            s[nt][3] = ex2(s[nt][3] - m1);
            sum0 += s[nt][0] + s[nt][1];
            sum1 += s[nt][2] + s[nt][3];
        }
        sum0 += __shfl_xor_sync(0xffffffffu, sum0, 1);
        sum0 += __shfl_xor_sync(0xffffffffu, sum0, 2);
        sum1 += __shfl_xor_sync(0xffffffffu, sum1, 1);
        sum1 += __shfl_xor_sync(0xffffffffu, sum1, 2);
        l0 = l0 * corr0 + sum0;
        l1 = l1 * corr1 + sum1;

#pragma unroll
        for (int nt = 0; nt < 8; nt++) {
            o[nt][0] *= corr0; o[nt][1] *= corr0;
            o[nt][2] *= corr1; o[nt][3] *= corr1;
        }

        // Stage P (tf32-rounded) into warp-private smem rows
        __syncwarp();
        float* Pp = sm + PS_OFF + (wid * 16 + g) * PSTR;
#pragma unroll
        for (int nt = 0; nt < 8; nt++) {
            int col = nt * 8 + 2 * c4;
            *(float2*)(Pp + col) =
                make_float2(tf32_round(s[nt][0]), tf32_round(s[nt][1]));
            *(float2*)(Pp + 8 * PSTR + col) =
                make_float2(tf32_round(s[nt][2]), tf32_round(s[nt][3]));
        }
        __syncwarp();

        // O += P @ V
        const float* Psp = sm + PS_OFF + (wid * 16 + g) * PSTR;
#pragma unroll
        for (int kk = 0; kk < 64; kk += 8) {
            uint32_t a[4];
            const float* pp = Psp + kk + c4;
            a[0] = __float_as_uint(pp[0]);
            a[1] = __float_as_uint(pp[8 * PSTR]);
            a[2] = __float_as_uint(pp[4]);
            a[3] = __float_as_uint(pp[8 * PSTR + 4]);
#pragma unroll
            for (int nt = 0; nt < 8; nt++) {
                uint32_t b[2];
                b[0] = __float_as_uint(Vsp[(kk + c4) * VSTR + nt * 8 + g]);
                b[1] = __float_as_uint(Vsp[(kk + c4 + 4) * VSTR + nt * 8 + g]);
                mma_tf32(o[nt], a, b);
            }
        }
        __syncthreads();  // all warps done with this KV buffer
    }

    // Epilogue: normalize, tf32-round (proj input), store to g_y [B,T,C]
    const float il0 = 1.0f / l0, il1 = 1.0f / l1;
    const int bi = bh / HH, h = bh % HH;
    const int r0 = q0 + wid * 16 + g;
    float* dst0 = g_y + ((size_t)(bi * TT + r0)) * CC + h * DD;
    float* dst1 = dst0 + 8 * CC;
#pragma unroll
    for (int nt = 0; nt < 8; nt++) {
        int col = nt * 8 + 2 * c4;
        *(float2*)(dst0 + col) = make_float2(tf32_round(o[nt][0] * il0),
                                             tf32_round(o[nt][1] * il0));
        *(float2*)(dst1 + col) = make_float2(tf32_round(o[nt][2] * il1),
                                             tf32_round(o[nt][3] * il1));
    }
}

// ---------------------------------------------------------------------------
extern "C" void kernel_launch(void* const* d_in, const int* in_sizes, int n_in,
                              void* d_out, int out_size)
{
    const float* x      = (const float*)d_in[0];
    const float* w_qkv  = (const float*)d_in[1];
    const float* b_qkv  = (const float*)d_in[2];
    const float* w_proj = (const float*)d_in[3];
    const float* b_proj = (const float*)d_in[4];
    float* out = (float*)d_out;

    cudaFuncSetAttribute(mm_mma_kernel,
                         cudaFuncAttributeMaxDynamicSharedMemorySize, SMEMB);
    cudaFuncSetAttribute(attn_mma_kernel,
                         cudaFuncAttributeMaxDynamicSharedMemorySize, ATT_SMEMB);

    // tf32 (RNA) rounding of all GEMM inputs, one launch
    cvt_all_kernel<<<CVT_BLOCKS, 256>>>(x, w_qkv, w_proj);

    // QKV: [8192 x 768] @ [768 x 2304]
    mm_mma_kernel<<<dim3(NQKV / 128, NTOK / 128), 128, SMEMB>>>(
        b_qkv, nullptr, NQKV, 0);
    // Attention: tf32 mma flash, 128-row Q tiles
    attn_mma_kernel<<<dim3(TT / 128, BB * HH), 256, ATT_SMEMB>>>();
    // Proj: [8192 x 768] @ [768 x 768]
    mm_mma_kernel<<<dim3(CC / 128, NTOK / 128), 128, SMEMB>>>(
        b_proj, out, CC, 1);
}

// round 13
// speedup vs baseline: 1.0681x; 1.0681x over previous
#include <cuda_runtime.h>
#include <cstdint>

// Problem constants
#define BB 8
#define TT 1024
#define CC 768
#define HH 12
#define DD 64
#define NTOK (BB * TT)      // 8192
#define NQKV (3 * CC)       // 2304

// Scratch (device globals; no runtime allocation allowed)
__device__ float g_q[BB * HH * TT * DD];   // [B,H,T,D], q pre-scaled by log2e/8
__device__ float g_k[BB * HH * TT * DD];   // [B,H,T,D]
__device__ float g_v[BB * HH * TT * DD];   // [B,H,D,T]  (TRANSPOSED for ldmatrix)
__device__ float g_y[BB * TT * CC];        // attention output (tf32-rounded)
__device__ float g_xc[NTOK * CC];          // x, tf32-rounded
__device__ float g_wqc[CC * NQKV];         // w_qkv, tf32-rounded
__device__ float g_wpc[CC * CC];           // w_proj, tf32-rounded

// ---------------------------------------------------------------------------
// Helpers (compute_80-level PTX only; no sm_103a-only features)
// ---------------------------------------------------------------------------
__device__ __forceinline__ uint32_t smem_u32(const void* p) {
    uint32_t a;
    asm("{ .reg .u64 t; cvta.to.shared.u64 t, %1; cvt.u32.u64 %0, t; }"
        : "=r"(a) : "l"(p));
    return a;
}
__device__ __forceinline__ uint32_t tf32_bits(float x) {
    uint32_t r;
    asm("cvt.rna.tf32.f32 %0, %1;" : "=r"(r) : "f"(x));
    return r;
}
__device__ __forceinline__ float tf32_round(float x) {
    return __uint_as_float(tf32_bits(x));
}
__device__ __forceinline__ float ex2(float x) {
    float y;
    asm("ex2.approx.ftz.f32 %0, %1;" : "=f"(y) : "f"(x));
    return y;
}
__device__ __forceinline__ void cp_async16(uint32_t dst, const void* src) {
    asm volatile("cp.async.ca.shared.global [%0], [%1], 16;"
                 :: "r"(dst), "l"(src));
}
#define CP_COMMIT() asm volatile("cp.async.commit_group;" ::: "memory")
#define CP_WAIT(n)  asm volatile("cp.async.wait_group %0;" :: "n"(n) : "memory")

// m16n8k8 tf32 mma: D += A*B, fp32 accumulate.
__device__ __forceinline__ void mma_tf32(float* d, const uint32_t* a,
                                         const uint32_t* b) {
    asm volatile(
        "mma.sync.aligned.m16n8k8.row.col.f32.tf32.tf32.f32 "
        "{%0,%1,%2,%3}, {%4,%5,%6,%7}, {%8,%9}, {%0,%1,%2,%3};"
        : "+f"(d[0]), "+f"(d[1]), "+f"(d[2]), "+f"(d[3])
        : "r"(a[0]), "r"(a[1]), "r"(a[2]), "r"(a[3]),
          "r"(b[0]), "r"(b[1]));
}

// ldmatrix x4: four 8x8 b16 matrices == four 8x4 b32 (tf32) submatrices.
// Lane L supplies the address of row (L%8) of matrix (L/8); lane L's output
// reg j = element (L/4, L%4) of matrix j.
#define LDM_X4(r0, r1, r2, r3, addr) \
    asm volatile("ldmatrix.sync.aligned.m8n8.x4.shared.b16 {%0,%1,%2,%3}, [%4];" \
                 : "=r"(r0), "=r"(r1), "=r"(r2), "=r"(r3) : "r"(addr))

// ---------------------------------------------------------------------------
// Single fused tf32 rounding pass over x, w_qkv, w_proj.
// ---------------------------------------------------------------------------
#define N4_X  (NTOK * CC / 4)     // 1572864
#define N4_WQ (CC * NQKV / 4)     // 442368
#define N4_WP (CC * CC / 4)       // 147456
#define CVT_BLOCKS ((N4_X + N4_WQ + N4_WP) / 256)   // 8448

__global__ __launch_bounds__(256) void cvt_all_kernel(
    const float* __restrict__ x, const float* __restrict__ wq,
    const float* __restrict__ wp)
{
    int i = blockIdx.x * 256 + threadIdx.x;
    const float* src;
    float* dst;
    if (i < N4_X) {
        src = x; dst = g_xc;
    } else if (i < N4_X + N4_WQ) {
        i -= N4_X; src = wq; dst = g_wqc;
    } else {
        i -= N4_X + N4_WQ; src = wp; dst = g_wpc;
    }
    float4 v = ((const float4*)src)[i];
    uint4 r;
    r.x = tf32_bits(v.x);
    r.y = tf32_bits(v.y);
    r.z = tf32_bits(v.z);
    r.w = tf32_bits(v.w);
    ((uint4*)dst)[i] = r;
}

// ---------------------------------------------------------------------------
// tf32 mma.sync GEMM (R9-proven config + ldmatrix A-frags).
// CTA 128x128, 256 thr (8 warps as 2m x 4n), warp tile 64x32, 2-stage.
// As: m-major [128][36]  (ldmatrix row bank = 4r+c, perfect permutation)
// Bs: k-major [32][136]  (136 = 8 mod 32 -> frag bank = 8c4+g, perfect)
// ---------------------------------------------------------------------------
#define KTILE 32
#define NIT (CC / KTILE)        // 24
#define ASTRIDE 36
#define BSTRIDE 136
#define ABYTES (128 * ASTRIDE * 4)   // 18432
#define BBYTES (KTILE * BSTRIDE * 4) // 17408
#define BUFBYTES (ABYTES + BBYTES)   // 35840
#define SMEMB (2 * BUFBYTES)         // 71680

__device__ __forceinline__ void mm_issue_tile(
    const float* __restrict__ A, const float* __restrict__ W,
    uint32_t sbuf, int m0, int n0, int k0, int Ntot, int tid)
{
    const uint32_t sA = sbuf;
    const uint32_t sB = sbuf + ABYTES;
#pragma unroll
    for (int i = 0; i < 4; i++) {
        int idx = tid + 256 * i;
        int m = idx >> 3, kq = idx & 7;
        cp_async16(sA + (m * ASTRIDE + kq * 4) * 4,
                   A + (size_t)(m0 + m) * CC + k0 + kq * 4);
    }
#pragma unroll
    for (int i = 0; i < 4; i++) {
        int idx = tid + 256 * i;
        int n4 = idx & 31, k = idx >> 5;
        cp_async16(sB + (k * BSTRIDE + n4 * 4) * 4,
                   W + (size_t)(k0 + k) * Ntot + n0 + n4 * 4);
    }
    CP_COMMIT();
}

__global__ void __launch_bounds__(256, 2) mm_mma_kernel(
    const float* __restrict__ bias, float* __restrict__ out,
    int Ntot, int mode)
{
    extern __shared__ __align__(16) char smem[];
    const float* A = (mode == 0) ? g_xc : g_y;
    const float* W = (mode == 0) ? g_wqc : g_wpc;

    const int tid = threadIdx.x;
    const int wid = tid >> 5;
    const int lane = tid & 31;
    const int g = lane >> 2;
    const int c4 = lane & 3;
    const int m0 = blockIdx.y * 128;
    const int n0 = blockIdx.x * 128;
    const int wm = (wid >> 2) * 64;
    const int wn = (wid & 3) * 32;
    const uint32_t sbase = smem_u32(smem);

    // ldmatrix lane geometry for A-type fragments
    const int arow_l = ((lane >> 3) & 1) * 8 + (lane & 7);  // 0..15
    const int acol_l = (lane >> 4) * 4;                     // 0 or 4

    float acc[4][4][4];
#pragma unroll
    for (int mt = 0; mt < 4; mt++)
#pragma unroll
        for (int nt = 0; nt < 4; nt++)
#pragma unroll
            for (int i = 0; i < 4; i++) acc[mt][nt][i] = 0.0f;

    mm_issue_tile(A, W, sbase, m0, n0, 0, Ntot, tid);

    for (int it = 0; it < NIT; it++) {
        const int buf = it & 1;
        if (it + 1 < NIT) {
            mm_issue_tile(A, W, sbase + (buf ^ 1) * BUFBYTES,
                          m0, n0, (it + 1) * KTILE, Ntot, tid);
            CP_WAIT(1);
        } else {
            CP_WAIT(0);
        }
        __syncthreads();

        const uint32_t aaddr =
            sbase + buf * BUFBYTES + ((wm + arow_l) * ASTRIDE + acol_l) * 4;
        const float* Bsp = (const float*)(smem + buf * BUFBYTES + ABYTES);

#pragma unroll
        for (int kk = 0; kk < KTILE; kk += 8) {
            uint32_t a[4][4], b[4][2];
#pragma unroll
            for (int mt = 0; mt < 4; mt++)
                LDM_X4(a[mt][0], a[mt][1], a[mt][2], a[mt][3],
                       aaddr + (mt * 16 * ASTRIDE + kk) * 4);
#pragma unroll
            for (int nt = 0; nt < 4; nt++) {
                const float* q = Bsp + (kk + c4) * BSTRIDE + wn + nt * 8 + g;
                b[nt][0] = __float_as_uint(q[0]);
                b[nt][1] = __float_as_uint(q[4 * BSTRIDE]);
            }
#pragma unroll
            for (int mt = 0; mt < 4; mt++)
#pragma unroll
                for (int nt = 0; nt < 4; nt++)
                    mma_tf32(acc[mt][nt], a[mt], b[nt]);
        }
        __syncthreads();
    }

    // Epilogue.  Fragment (mt,nt): rows g,g+8; cols 2c4,2c4+1.
    if (mode == 1) {
#pragma unroll
        for (int mt = 0; mt < 4; mt++) {
#pragma unroll
            for (int nt = 0; nt < 4; nt++) {
                int mg = m0 + wm + mt * 16 + g;
                int ng = n0 + wn + nt * 8 + 2 * c4;
                float b0 = bias[ng], b1 = bias[ng + 1];
                float2 v0 = make_float2(acc[mt][nt][0] + b0, acc[mt][nt][1] + b1);
                float2 v1 = make_float2(acc[mt][nt][2] + b0, acc[mt][nt][3] + b1);
                *(float2*)(out + (size_t)mg * CC + ng) = v0;
                *(float2*)(out + (size_t)(mg + 8) * CC + ng) = v1;
            }
        }
    } else {
        // q scale folds 1/sqrt(64) AND log2(e): attention softmax uses ex2.
#pragma unroll
        for (int mt = 0; mt < 4; mt++) {
#pragma unroll
            for (int nt = 0; nt < 4; nt++) {
                int mg = m0 + wm + mt * 16 + g;
                int ng = n0 + wn + nt * 8 + 2 * c4;
                int region = ng / CC;             // 0=q 1=k 2=v
                int cp = ng - region * CC;
                int h = cp >> 6, d = cp & 63;     // d even
                int bi = mg >> 10, t = mg & 1023;
                float b0 = bias[ng], b1 = bias[ng + 1];
                if (region == 2) {
                    // g_v layout [B,H,D,T]
                    float* dst = g_v + ((size_t)(bi * HH + h) * DD + d) * TT + t;
                    dst[0]      = tf32_round(acc[mt][nt][0] + b0);
                    dst[TT]     = tf32_round(acc[mt][nt][1] + b1);
                    dst[8]      = tf32_round(acc[mt][nt][2] + b0);
                    dst[TT + 8] = tf32_round(acc[mt][nt][3] + b1);
                } else {
                    float sc = (region == 0) ? 0.18033688011112042f : 1.0f;
                    float* base = (region == 0) ? g_q : g_k;
                    float* dst =
                        base + ((size_t)(bi * HH + h) * TT + t) * DD + d;
                    float2 v0 = make_float2(tf32_round((acc[mt][nt][0] + b0) * sc),
                                            tf32_round((acc[mt][nt][1] + b1) * sc));
                    float2 v1 = make_float2(tf32_round((acc[mt][nt][2] + b0) * sc),
                                            tf32_round((acc[mt][nt][3] + b1) * sc));
                    *(float2*)dst = v0;
                    *(float2*)(dst + 8 * DD) = v1;
                }
            }
        }
    }
}

// ---------------------------------------------------------------------------
// Causal flash attention on tf32 mma.sync + ldmatrix fragment loads.
// CTA = 128 Q rows x one (b,h); 8 warps, warp w owns rows w*16..w*16+15.
// KV tiles of 64, cp.async double-buffered.  V is [D,T] per head (transposed
// at QKV epilogue) so PV B-fragments are ldmatrix-able.
// All strides 68: ldmatrix row bank = 4r + c, perfect permutation.
// ---------------------------------------------------------------------------
#define AKV 64
#define QSTR 68
#define KSTR 68
#define VSTR 68
#define PSTR 68
#define PS_OFF (128 * QSTR)                 // 8704
#define KV_OFF (PS_OFF + 128 * PSTR)        // 17408
#define KBUF_F (AKV * KSTR)                 // 4352
#define KVBUF_F (KBUF_F + AKV * VSTR)       // 8704
#define ATT_SMEMF (KV_OFF + 2 * KVBUF_F)    // 34816
#define ATT_SMEMB (ATT_SMEMF * 4)           // 139264

__global__ __launch_bounds__(256, 1) void attn_mma_kernel()
{
    extern __shared__ __align__(16) float sm[];
    const int tid = threadIdx.x;
    const int wid = tid >> 5;
    const int lane = tid & 31;
    const int g = lane >> 2;      // 0..7
    const int c4 = lane & 3;      // 0..3
    const int qt = 7 - (int)blockIdx.x;   // heavy tiles launch first
    const int bh = blockIdx.y;
    const int q0 = qt * 128;

    const float* Qg = g_q + (size_t)bh * (TT * DD) + (size_t)q0 * DD;
    const float* Kg = g_k + (size_t)bh * (TT * DD);
    const float* Vg = g_v + (size_t)bh * (DD * TT);   // [D][T]
    const uint32_t sb = smem_u32(sm);

    // ldmatrix lane geometry
    const int arow_l = ((lane >> 3) & 1) * 8 + (lane & 7);  // 0..15
    const int acol_l = (lane >> 4) * 4;                     // 0 or 4

    // Prologue: Q tile (128x64) + KV tile 0, one cp.async group.
#pragma unroll
    for (int i = 0; i < 8; i++) {
        int idx = tid + 256 * i;
        int r = idx >> 4, c = (idx & 15) * 4;
        cp_async16(sb + (r * QSTR + c) * 4, Qg + r * DD + c);
    }
#pragma unroll
    for (int i = 0; i < 4; i++) {
        int idx = tid + 256 * i;
        int r = idx >> 4, c = (idx & 15) * 4;
        cp_async16(sb + (KV_OFF + r * KSTR + c) * 4, Kg + r * DD + c);
        cp_async16(sb + (KV_OFF + KBUF_F + r * VSTR + c) * 4,
                   Vg + (size_t)r * TT + c);
    }
    CP_COMMIT();

    float o[8][4];
#pragma unroll
    for (int nt = 0; nt < 8; nt++)
#pragma unroll
        for (int i = 0; i < 4; i++) o[nt][i] = 0.0f;
    float m0 = -1e30f, m1 = -1e30f, l0 = 0.0f, l1 = 0.0f;

    const int ntiles = 2 * qt + 2;
    const uint32_t qaddr = sb + ((wid * 16 + arow_l) * QSTR + acol_l) * 4;
    const uint32_t paddr =
        sb + (PS_OFF + (wid * 16 + arow_l) * PSTR + acol_l) * 4;

    for (int j = 0; j < ntiles; j++) {
        const int buf = j & 1;
        if (j + 1 < ntiles) {
            const float* Kg2 = Kg + (size_t)(j + 1) * AKV * DD;
            const float* Vg2 = Vg + (j + 1) * AKV;   // column offset in [D][T]
            const uint32_t kvb = sb + (KV_OFF + (buf ^ 1) * KVBUF_F) * 4;
#pragma unroll
            for (int i = 0; i < 4; i++) {
                int idx = tid + 256 * i;
                int r = idx >> 4, c = (idx & 15) * 4;
                cp_async16(kvb + (r * KSTR + c) * 4, Kg2 + r * DD + c);
                cp_async16(kvb + (KBUF_F + r * VSTR + c) * 4,
                           Vg2 + (size_t)r * TT + c);
            }
            CP_COMMIT();
            CP_WAIT(1);
        } else {
            CP_WAIT(0);
        }
        __syncthreads();

        const uint32_t kbase = sb + (KV_OFF + buf * KVBUF_F) * 4 +
                               (arow_l * KSTR + acol_l) * 4;
        const uint32_t vbase = kbase + KBUF_F * 4;

        // S = Q @ K^T  (log2 domain; Q pre-scaled)
        float s[8][4];
#pragma unroll
        for (int nt = 0; nt < 8; nt++)
#pragma unroll
            for (int i = 0; i < 4; i++) s[nt][i] = 0.0f;

#pragma unroll
        for (int kk = 0; kk < 64; kk += 8) {
            uint32_t a[4];
            LDM_X4(a[0], a[1], a[2], a[3], qaddr + kk * 4);
#pragma unroll
            for (int i = 0; i < 4; i++) {
                uint32_t r0, r1, r2, r3;
                LDM_X4(r0, r1, r2, r3, kbase + (i * 16 * KSTR + kk) * 4);
                uint32_t b0[2] = {r0, r2}, b1[2] = {r1, r3};
                mma_tf32(s[2 * i], a, b0);
                mma_tf32(s[2 * i + 1], a, b1);
            }
        }

        // Causal mask (only the two diagonal-straddling tiles need it)
        if (j >= 2 * qt) {
            const int off = q0 - j * AKV;   // 0 or -64
            const int r0 = wid * 16 + g, r1 = r0 + 8;
#pragma unroll
            for (int nt = 0; nt < 8; nt++) {
                int col = nt * 8 + 2 * c4;
                if (col     > r0 + off) s[nt][0] = -1e30f;
                if (col + 1 > r0 + off) s[nt][1] = -1e30f;
                if (col     > r1 + off) s[nt][2] = -1e30f;
                if (col + 1 > r1 + off) s[nt][3] = -1e30f;
            }
        }

        // Online softmax (rows g and g+8; quad-wide reduction)
        float mx0 = -1e30f, mx1 = -1e30f;
#pragma unroll
        for (int nt = 0; nt < 8; nt++) {
            mx0 = fmaxf(mx0, fmaxf(s[nt][0], s[nt][1]));
            mx1 = fmaxf(mx1, fmaxf(s[nt][2], s[nt][3]));
        }
        mx0 = fmaxf(mx0, __shfl_xor_sync(0xffffffffu, mx0, 1));
        mx0 = fmaxf(mx0, __shfl_xor_sync(0xffffffffu, mx0, 2));
        mx1 = fmaxf(mx1, __shfl_xor_sync(0xffffffffu, mx1, 1));
        mx1 = fmaxf(mx1, __shfl_xor_sync(0xffffffffu, mx1, 2));

        float mn0 = fmaxf(m0, mx0), mn1 = fmaxf(m1, mx1);
        float corr0 = ex2(m0 - mn0), corr1 = ex2(m1 - mn1);
        m0 = mn0; m1 = mn1;

        float sum0 = 0.0f, sum1 = 0.0f;
#pragma unroll
        for (int nt = 0; nt < 8; nt++) {
            s[nt][0] = ex2(s[nt][0] - m0);
            s[nt][1] = ex2(s[nt][1] - m0);
            s[nt][2] = ex2(s[nt][2] - m1);
            s[nt][3] = ex2(s[nt][3] - m1);
            sum0 += s[nt][0] + s[nt][1];
            sum1 += s[nt][2] + s[nt][3];
        }
        sum0 += __shfl_xor_sync(0xffffffffu, sum0, 1);
        sum0 += __shfl_xor_sync(0xffffffffu, sum0, 2);
        sum1 += __shfl_xor_sync(0xffffffffu, sum1, 1);
        sum1 += __shfl_xor_sync(0xffffffffu, sum1, 2);
        l0 = l0 * corr0 + sum0;
        l1 = l1 * corr1 + sum1;

#pragma unroll
        for (int nt = 0; nt < 8; nt++) {
            o[nt][0] *= corr0; o[nt][1] *= corr0;
            o[nt][2] *= corr1; o[nt][3] *= corr1;
        }

        // Stage P (tf32-rounded) into warp-private smem rows
        __syncwarp();
        float* Pp = sm + PS_OFF + (wid * 16 + g) * PSTR;
#pragma unroll
        for (int nt = 0; nt < 8; nt++) {
            int col = nt * 8 + 2 * c4;
            *(float2*)(Pp + col) =
                make_float2(tf32_round(s[nt][0]), tf32_round(s[nt][1]));
            *(float2*)(Pp + 8 * PSTR + col) =
                make_float2(tf32_round(s[nt][2]), tf32_round(s[nt][3]));
        }
        __syncwarp();

        // O += P @ V   (V tile is [d][t]; B-frags ldmatrix'd like K)
#pragma unroll
        for (int kk = 0; kk < 64; kk += 8) {
            uint32_t a[4];
            LDM_X4(a[0], a[1], a[2], a[3], paddr + kk * 4);
#pragma unroll
            for (int i = 0; i < 4; i++) {
                uint32_t r0, r1, r2, r3;
                LDM_X4(r0, r1, r2, r3, vbase + (i * 16 * VSTR + kk) * 4);
                uint32_t b0[2] = {r0, r2}, b1[2] = {r1, r3};
                mma_tf32(o[2 * i], a, b0);
                mma_tf32(o[2 * i + 1], a, b1);
            }
        }
        __syncthreads();  // all warps done with this KV buffer
    }

    // Epilogue: normalize, tf32-round (proj input), store to g_y [B,T,C]
    const float il0 = 1.0f / l0, il1 = 1.0f / l1;
    const int bi = bh / HH, h = bh % HH;
    const int r0 = q0 + wid * 16 + g;
    float* dst0 = g_y + ((size_t)(bi * TT + r0)) * CC + h * DD;
    float* dst1 = dst0 + 8 * CC;
#pragma unroll
    for (int nt = 0; nt < 8; nt++) {
        int col = nt * 8 + 2 * c4;
        *(float2*)(dst0 + col) = make_float2(tf32_round(o[nt][0] * il0),
                                             tf32_round(o[nt][1] * il0));
        *(float2*)(dst1 + col) = make_float2(tf32_round(o[nt][2] * il1),
                                             tf32_round(o[nt][3] * il1));
    }
}

// ---------------------------------------------------------------------------
extern "C" void kernel_launch(void* const* d_in, const int* in_sizes, int n_in,
                              void* d_out, int out_size)
{
    const float* x      = (const float*)d_in[0];
    const float* w_qkv  = (const float*)d_in[1];
    const float* b_qkv  = (const float*)d_in[2];
    const float* w_proj = (const float*)d_in[3];
    const float* b_proj = (const float*)d_in[4];
    float* out = (float*)d_out;

    cudaFuncSetAttribute(mm_mma_kernel,
                         cudaFuncAttributeMaxDynamicSharedMemorySize, SMEMB);
    cudaFuncSetAttribute(attn_mma_kernel,
                         cudaFuncAttributeMaxDynamicSharedMemorySize, ATT_SMEMB);

    // tf32 (RNA) rounding of all GEMM inputs, one launch
    cvt_all_kernel<<<CVT_BLOCKS, 256>>>(x, w_qkv, w_proj);

    // QKV: [8192 x 768] @ [768 x 2304]
    mm_mma_kernel<<<dim3(NQKV / 128, NTOK / 128), 256, SMEMB>>>(
        b_qkv, nullptr, NQKV, 0);
    // Attention: tf32 mma flash, 128-row Q tiles, ldmatrix frags
    attn_mma_kernel<<<dim3(TT / 128, BB * HH), 256, ATT_SMEMB>>>();
    // Proj: [8192 x 768] @ [768 x 768]
    mm_mma_kernel<<<dim3(CC / 128, NTOK / 128), 256, SMEMB>>>(
        b_proj, out, CC, 1);
}